// round 1
// baseline (speedup 1.0000x reference)
#include <cuda_runtime.h>
#include <math.h>
#include <stdint.h>

// ---------------- scratch (static device memory; no allocs allowed) ----------
__device__ float g_conv[205520896];   // max conv out: 256*16*224*224 (822 MB)
__device__ float g_poolA[51380224];   // 256*16*112*112 (205 MB), reused for pool3 out
__device__ float g_poolB[25690112];   // 256*32*56*56  (103 MB)
__device__ double g_sum[64];
__device__ double g_sumsq[64];
__device__ float g_scale[64];
__device__ float g_shift[64];

// ---------------- BN statistics helpers -------------------------------------
__global__ void zero_stats_k() {
    int i = threadIdx.x;
    if (i < 64) { g_sum[i] = 0.0; g_sumsq[i] = 0.0; }
}

__global__ void stats_k(const float* __restrict__ d, int B, int C, int HW) {
    int c = blockIdx.y;
    int tid = threadIdx.x;
    float s = 0.f, s2 = 0.f;
    for (int n = blockIdx.x; n < B; n += gridDim.x) {
        const float* p = d + ((size_t)n * C + c) * (size_t)HW;
        for (int i = tid; i < HW; i += blockDim.x) {
            float v = p[i];
            s += v; s2 += v * v;
        }
    }
    __shared__ float rs[256], rs2[256];
    rs[tid] = s; rs2[tid] = s2;
    __syncthreads();
    for (int k = 128; k > 0; k >>= 1) {
        if (tid < k) { rs[tid] += rs[tid + k]; rs2[tid] += rs2[tid + k]; }
        __syncthreads();
    }
    if (tid == 0) {
        atomicAdd(&g_sum[c], (double)rs[0]);
        atomicAdd(&g_sumsq[c], (double)rs2[0]);
    }
}

__global__ void finalize_k(const float* __restrict__ gam, const float* __restrict__ bet,
                           int C, double inv_cnt) {
    int c = threadIdx.x;
    if (c < C) {
        double mean = g_sum[c] * inv_cnt;
        double var = g_sumsq[c] * inv_cnt - mean * mean;
        float sc = gam[c] * rsqrtf((float)var + 1e-5f);
        g_scale[c] = sc;
        g_shift[c] = bet[c] - sc * (float)mean;
    }
}

// ---------------- direct 3x3 conv, SAME pad, stride 1 -----------------------
// Block = 128 threads. Tile = 32(x) x 16(y) outputs; each thread: 4 px (x) x 8 co.
template<int CI>
__launch_bounds__(128)
__global__ void conv3x3_k(const float* __restrict__ in, const float* __restrict__ w,
                          const float* __restrict__ bias, float* __restrict__ out,
                          int CO, int H, int W, int tiles_x) {
    __shared__ float s_in[18][35];          // 16+2 rows, 32+2 cols (pad 35 vs banks)
    __shared__ float s_w[CI * 8 * 9];
    const int n   = blockIdx.z;
    const int cog = blockIdx.y;
    const int tile = blockIdx.x;
    const int tx = tile % tiles_x, ty = tile / tiles_x;
    const int tid = threadIdx.x;

    for (int i = tid; i < CI * 8 * 9; i += 128)
        s_w[i] = w[(size_t)(cog * 8) * CI * 9 + i];

    const int px = (tid & 7) * 4;   // 0..28
    const int py = tid >> 3;        // 0..15
    const int gx0 = tx * 32 - 1;
    const int gy0 = ty * 16 - 1;

    float acc[8][4];
    #pragma unroll
    for (int co = 0; co < 8; co++)
        #pragma unroll
        for (int p = 0; p < 4; p++) acc[co][p] = 0.f;

    for (int ci = 0; ci < CI; ci++) {
        __syncthreads();
        const float* ip = in + ((size_t)n * CI + ci) * (size_t)H * W;
        for (int i = tid; i < 18 * 34; i += 128) {
            int r = i / 34, c = i % 34;
            int gy = gy0 + r, gx = gx0 + c;
            float v = 0.f;
            if (gy >= 0 && gy < H && gx >= 0 && gx < W) v = ip[(size_t)gy * W + gx];
            s_in[r][c] = v;
        }
        __syncthreads();

        float iv[3][6];
        #pragma unroll
        for (int ky = 0; ky < 3; ky++)
            #pragma unroll
            for (int j = 0; j < 6; j++)
                iv[ky][j] = s_in[py + ky][px + j];

        #pragma unroll
        for (int co = 0; co < 8; co++) {
            const float* wp = &s_w[(co * CI + ci) * 9];
            #pragma unroll
            for (int ky = 0; ky < 3; ky++)
                #pragma unroll
                for (int kx = 0; kx < 3; kx++) {
                    float wv = wp[ky * 3 + kx];
                    #pragma unroll
                    for (int p = 0; p < 4; p++)
                        acc[co][p] = fmaf(iv[ky][kx + p], wv, acc[co][p]);
                }
        }
    }

    const int y = ty * 16 + py;
    if (y < H) {
        #pragma unroll
        for (int co = 0; co < 8; co++) {
            int cg = cog * 8 + co;
            float b = bias[cg];
            size_t base = (((size_t)n * CO + cg) * H + y) * (size_t)W;
            #pragma unroll
            for (int p = 0; p < 4; p++) {
                int x = tx * 32 + px + p;
                if (x < W) out[base + x] = acc[co][p] + b;
            }
        }
    }
}

// ---------------- BN affine + ReLU + 2x2 maxpool -----------------------------
__global__ void bn_relu_pool_k(const float* __restrict__ in, float* __restrict__ out,
                               int C, int H, int W, long long total) {
    long long idx = (long long)blockIdx.x * blockDim.x + threadIdx.x;
    if (idx >= total) return;
    int W2 = W >> 1, H2 = H >> 1;
    int x2 = (int)(idx % W2);
    long long r = idx / W2;
    int y2 = (int)(r % H2); r /= H2;
    int c  = (int)(r % C);
    int n  = (int)(r / C);
    const float* p = in + (((size_t)n * C + c) * H + 2 * y2) * (size_t)W + 2 * x2;
    float a = g_scale[c], s = g_shift[c];
    float v0 = fmaf(p[0], a, s);
    float v1 = fmaf(p[1], a, s);
    float v2 = fmaf(p[W], a, s);
    float v3 = fmaf(p[W + 1], a, s);
    float m = fmaxf(fmaxf(v0, v1), fmaxf(v2, v3));
    out[idx] = fmaxf(m, 0.f);
}

// ---------------- head: GAP + fc1 + LN + quantum circuit + fc2/fc3 -----------
__global__ void head_k(const float* __restrict__ pooled,   // (B,64,28,28)
                       const float* __restrict__ fc1_w, const float* __restrict__ fc1_b,
                       const float* __restrict__ ln_g,  const float* __restrict__ ln_b,
                       const float* __restrict__ qp,
                       const float* __restrict__ fc2_w, const float* __restrict__ fc2_b,
                       const float* __restrict__ fc3_w, const float* __restrict__ fc3_b,
                       float* __restrict__ out) {
    const int n = blockIdx.x;
    const int tid = threadIdx.x;
    const int warp = tid >> 5, lane = tid & 31;
    __shared__ float chm[64];
    __shared__ float qin[5];
    __shared__ float qres;

    // channel means over 28*28 = 784
    const float* base = pooled + (size_t)n * 64 * 784;
    for (int j = 0; j < 8; j++) {
        int c = warp * 8 + j;
        const float* p = base + (size_t)c * 784;
        float s = 0.f;
        for (int i = lane; i < 784; i += 32) s += p[i];
        #pragma unroll
        for (int o = 16; o > 0; o >>= 1) s += __shfl_down_sync(0xffffffffu, s, o);
        if (lane == 0) chm[c] = s * (1.0f / 784.0f);
    }
    __syncthreads();

    // fc1 + layernorm (thread 0)
    if (tid == 0) {
        float h[5];
        #pragma unroll
        for (int o = 0; o < 5; o++) {
            float s = fc1_b[o];
            for (int i = 0; i < 64; i++) s += chm[i] * fc1_w[i * 5 + o];
            h[o] = s;
        }
        float mu = 0.f;
        #pragma unroll
        for (int o = 0; o < 5; o++) mu += h[o];
        mu *= 0.2f;
        float var = 0.f;
        #pragma unroll
        for (int o = 0; o < 5; o++) { float d = h[o] - mu; var += d * d; }
        var *= 0.2f;
        float r = rsqrtf(var + 1e-5f);
        #pragma unroll
        for (int o = 0; o < 5; o++) qin[o] = ln_g[o] * (h[o] - mu) * r + ln_b[o];
    }
    __syncthreads();

    // 5-qubit statevector: amplitude per lane (warp 0). wire i -> bit (1<<(4-i))
    if (warp == 0) {
        float are = (lane == 0) ? 1.f : 0.f, aim = 0.f;
        const unsigned fm = 0xffffffffu;
        for (int l = 0; l < 3; l++) {
            // RX(inputs[i]) on each wire
            #pragma unroll
            for (int i = 0; i < 5; i++) {
                int m = 1 << (4 - i);
                float sn, cs; sincosf(qin[i] * 0.5f, &sn, &cs);
                float pre = __shfl_xor_sync(fm, are, m);
                float pim = __shfl_xor_sync(fm, aim, m);
                float nre = cs * are + sn * pim;   // c*a + (-i s)*partner
                float nim = cs * aim - sn * pre;
                are = nre; aim = nim;
            }
            // RY(w[l*10+i]) then RZ(w[l*10+i+5]) on each wire
            #pragma unroll
            for (int i = 0; i < 5; i++) {
                int m = 1 << (4 - i);
                float sy, cy; sincosf(qp[l * 10 + i] * 0.5f, &sy, &cy);
                float pre = __shfl_xor_sync(fm, are, m);
                float pim = __shfl_xor_sync(fm, aim, m);
                float sgn = (lane & m) ? sy : -sy;  // bit0: c*s0 - s*s1 ; bit1: s*s0 + c*s1
                float nre = cy * are + sgn * pre;
                float nim = cy * aim + sgn * pim;
                float sz, cz; sincosf(qp[l * 10 + i + 5] * 0.5f, &sz, &cz);
                float zg = (lane & m) ? -sz : sz;   // e^{-i t/2} on bit0, conj on bit1
                are = nre * cz + zg * nim;
                aim = nim * cz - zg * nre;
            }
            // CNOT ring (0,1)(1,2)(2,3)(3,4)(4,0)
            const int cw[5] = {0, 1, 2, 3, 4};
            const int tw[5] = {1, 2, 3, 4, 0};
            #pragma unroll
            for (int k = 0; k < 5; k++) {
                int mc = 1 << (4 - cw[k]);
                int mt = 1 << (4 - tw[k]);
                int src = (lane & mc) ? (lane ^ mt) : lane;
                are = __shfl_sync(fm, are, src);
                aim = __shfl_sync(fm, aim, src);
            }
        }
        float p = are * are + aim * aim;
        float sgn = (__popc(lane & 28) & 1) ? -1.f : 1.f;  // Z on wires 0,1,2
        float v = p * sgn;
        #pragma unroll
        for (int o = 16; o > 0; o >>= 1) v += __shfl_down_sync(fm, v, o);
        if (lane == 0) qres = v;
    }
    __syncthreads();

    if (tid == 0) {
        float q = qres;
        float l0 = fc3_b[0], l1 = fc3_b[1];
        for (int j = 0; j < 32; j++) {
            float h2 = fmaxf(q * fc2_w[j] + fc2_b[j], 0.f);
            l0 += h2 * fc3_w[j * 2 + 0];
            l1 += h2 * fc3_w[j * 2 + 1];
        }
        float mx = fmaxf(l0, l1);
        float lse = mx + logf(expf(l0 - mx) + expf(l1 - mx));
        out[n * 2 + 0] = l0 - lse;
        out[n * 2 + 1] = l1 - lse;
    }
}

// ---------------- host launcher ----------------------------------------------
extern "C" void kernel_launch(void* const* d_in, const int* in_sizes, int n_in,
                              void* d_out, int out_size) {
    const float* x    = (const float*)d_in[0];
    const float* c1w  = (const float*)d_in[1];
    const float* c1b  = (const float*)d_in[2];
    const float* bn1g = (const float*)d_in[3];
    const float* bn1b = (const float*)d_in[4];
    const float* c2w  = (const float*)d_in[5];
    const float* c2b  = (const float*)d_in[6];
    const float* bn2g = (const float*)d_in[7];
    const float* bn2b = (const float*)d_in[8];
    const float* c3w  = (const float*)d_in[9];
    const float* c3b  = (const float*)d_in[10];
    const float* bn3g = (const float*)d_in[11];
    const float* bn3b = (const float*)d_in[12];
    const float* fc1w = (const float*)d_in[13];
    const float* fc1b = (const float*)d_in[14];
    const float* lng  = (const float*)d_in[15];
    const float* lnb  = (const float*)d_in[16];
    const float* qp   = (const float*)d_in[17];
    const float* fc2w = (const float*)d_in[18];
    const float* fc2b = (const float*)d_in[19];
    const float* fc3w = (const float*)d_in[20];
    const float* fc3b = (const float*)d_in[21];
    float* out = (float*)d_out;

    float *conv, *poolA, *poolB;
    cudaGetSymbolAddress((void**)&conv,  g_conv);
    cudaGetSymbolAddress((void**)&poolA, g_poolA);
    cudaGetSymbolAddress((void**)&poolB, g_poolB);

    const int B = 256;

    // ---- Layer 1: conv(1->16) @224 ----
    {
        int H = 224, W = 224, CO = 16;
        int txs = (W + 31) / 32, tys = (H + 15) / 16;
        conv3x3_k<1><<<dim3(txs * tys, CO / 8, B), 128>>>(x, c1w, c1b, conv, CO, H, W, txs);
        zero_stats_k<<<1, 64>>>();
        stats_k<<<dim3(64, CO), 256>>>(conv, B, CO, H * W);
        finalize_k<<<1, 64>>>(bn1g, bn1b, CO, 1.0 / ((double)B * H * W));
        long long tot = (long long)B * CO * (H / 2) * (W / 2);
        bn_relu_pool_k<<<(unsigned)((tot + 255) / 256), 256>>>(conv, poolA, CO, H, W, tot);
    }
    // ---- Layer 2: conv(16->32) @112 ----
    {
        int H = 112, W = 112, CO = 32;
        int txs = (W + 31) / 32, tys = (H + 15) / 16;
        conv3x3_k<16><<<dim3(txs * tys, CO / 8, B), 128>>>(poolA, c2w, c2b, conv, CO, H, W, txs);
        zero_stats_k<<<1, 64>>>();
        stats_k<<<dim3(64, CO), 256>>>(conv, B, CO, H * W);
        finalize_k<<<1, 64>>>(bn2g, bn2b, CO, 1.0 / ((double)B * H * W));
        long long tot = (long long)B * CO * (H / 2) * (W / 2);
        bn_relu_pool_k<<<(unsigned)((tot + 255) / 256), 256>>>(conv, poolB, CO, H, W, tot);
    }
    // ---- Layer 3: conv(32->64) @56 ----
    {
        int H = 56, W = 56, CO = 64;
        int txs = (W + 31) / 32, tys = (H + 15) / 16;
        conv3x3_k<32><<<dim3(txs * tys, CO / 8, B), 128>>>(poolB, c3w, c3b, conv, CO, H, W, txs);
        zero_stats_k<<<1, 64>>>();
        stats_k<<<dim3(64, CO), 256>>>(conv, B, CO, H * W);
        finalize_k<<<1, 64>>>(bn3g, bn3b, CO, 1.0 / ((double)B * H * W));
        long long tot = (long long)B * CO * (H / 2) * (W / 2);
        bn_relu_pool_k<<<(unsigned)((tot + 255) / 256), 256>>>(conv, poolA, CO, H, W, tot);
    }
    // ---- Head ----
    head_k<<<B, 256>>>(poolA, fc1w, fc1b, lng, lnb, qp, fc2w, fc2b, fc3w, fc3b, out);
}

// round 3
// speedup vs baseline: 1.2085x; 1.2085x over previous
#include <cuda_runtime.h>
#include <math.h>
#include <stdint.h>

// ---------------- scratch (static device memory; no allocs allowed) ----------
__device__ float g_conv[102760448];   // max stored conv out: 256*32*112*112 (411 MB)
__device__ float g_poolA[51380224];   // 256*16*112*112 (205 MB); also pool3 out (51 MB)
__device__ float g_poolB[25690112];   // 256*32*56*56  (103 MB)
__device__ float g_psum[3 * 64 * 512];
__device__ float g_psumsq[3 * 64 * 512];
__device__ float g_scale[64];
__device__ float g_shift[64];

// ---------------- zero partial-stat buffers ----------------------------------
__global__ void zero_partials_k() {
    int i = blockIdx.x * blockDim.x + threadIdx.x;
    if (i < 3 * 64 * 512) { g_psum[i] = 0.f; g_psumsq[i] = 0.f; }
}

// ---------------- finalize: reduce partials -> scale/shift --------------------
__global__ void finalize_k(const float* __restrict__ gam, const float* __restrict__ bet,
                           int C, int layer, double inv_cnt) {
    int c = threadIdx.x;
    if (c < C) {
        const float* ps = &g_psum[(layer * 64 + c) * 512];
        const float* pq = &g_psumsq[(layer * 64 + c) * 512];
        double S = 0.0, Q = 0.0;
        for (int i = 0; i < 512; i++) { S += (double)ps[i]; Q += (double)pq[i]; }
        double mean = S * inv_cnt;
        double var = Q * inv_cnt - mean * mean;
        float sc = gam[c] * rsqrtf((float)var + 1e-5f);
        g_scale[c] = sc;
        g_shift[c] = bet[c] - sc * (float)mean;
    }
}

// ---------------- direct 3x3 conv, SAME pad, stride 1, fused BN stats --------
// Block = 128 threads. Tile = 32(x) x 16(y) outputs; each thread: 4 px (x) x 8 co.
template<int CI, bool STORE>
__launch_bounds__(128)
__global__ void conv3x3_k(const float* __restrict__ in, const float* __restrict__ w,
                          const float* __restrict__ bias, float* __restrict__ out,
                          int CO, int H, int W, int tiles_x, int layer) {
    __shared__ float s_in[18][35];
    __shared__ float s_w[CI * 8 * 9];
    __shared__ float redS[8][4], redQ[8][4];
    const int n   = blockIdx.z;
    const int cog = blockIdx.y;
    const int tile = blockIdx.x;
    const int tx = tile % tiles_x, ty = tile / tiles_x;
    const int tid = threadIdx.x;
    const int warp = tid >> 5, lane = tid & 31;

    for (int i = tid; i < CI * 8 * 9; i += 128)
        s_w[i] = w[(size_t)(cog * 8) * CI * 9 + i];

    const int px = (tid & 7) * 4;
    const int py = tid >> 3;
    const int gx0 = tx * 32 - 1;
    const int gy0 = ty * 16 - 1;

    float acc[8][4];
    #pragma unroll
    for (int co = 0; co < 8; co++)
        #pragma unroll
        for (int p = 0; p < 4; p++) acc[co][p] = 0.f;

    for (int ci = 0; ci < CI; ci++) {
        __syncthreads();
        const float* ip = in + ((size_t)n * CI + ci) * (size_t)H * W;
        for (int i = tid; i < 18 * 34; i += 128) {
            int r = i / 34, c = i % 34;
            int gy = gy0 + r, gx = gx0 + c;
            float v = 0.f;
            if (gy >= 0 && gy < H && gx >= 0 && gx < W) v = ip[(size_t)gy * W + gx];
            s_in[r][c] = v;
        }
        __syncthreads();

        float iv[3][6];
        #pragma unroll
        for (int ky = 0; ky < 3; ky++)
            #pragma unroll
            for (int j = 0; j < 6; j++)
                iv[ky][j] = s_in[py + ky][px + j];

        #pragma unroll
        for (int co = 0; co < 8; co++) {
            const float* wp = &s_w[(co * CI + ci) * 9];
            #pragma unroll
            for (int ky = 0; ky < 3; ky++)
                #pragma unroll
                for (int kx = 0; kx < 3; kx++) {
                    float wv = wp[ky * 3 + kx];
                    #pragma unroll
                    for (int p = 0; p < 4; p++)
                        acc[co][p] = fmaf(iv[ky][kx + p], wv, acc[co][p]);
                }
        }
    }

    // epilogue: optional store + per-channel stats accumulation
    const int y = ty * 16 + py;
    const bool yv = (y < H);
    #pragma unroll
    for (int co = 0; co < 8; co++) {
        int cg = cog * 8 + co;
        float b = bias[cg];
        size_t base = (((size_t)n * CO + cg) * H + y) * (size_t)W;
        float s = 0.f, q = 0.f;
        #pragma unroll
        for (int p = 0; p < 4; p++) {
            int x = tx * 32 + px + p;
            float v = acc[co][p] + b;
            bool valid = yv && (x < W);
            if (STORE && valid) out[base + x] = v;
            if (valid) { s += v; q += v * v; }
        }
        #pragma unroll
        for (int o = 16; o > 0; o >>= 1) {
            s += __shfl_down_sync(0xffffffffu, s, o);
            q += __shfl_down_sync(0xffffffffu, q, o);
        }
        if (lane == 0) { redS[co][warp] = s; redQ[co][warp] = q; }
    }
    __syncthreads();
    if (tid < 8) {
        float S = redS[tid][0] + redS[tid][1] + redS[tid][2] + redS[tid][3];
        float Q = redQ[tid][0] + redQ[tid][1] + redQ[tid][2] + redQ[tid][3];
        int slot = (blockIdx.x + blockIdx.z * 977) & 511;
        int c = cog * 8 + tid;
        atomicAdd(&g_psum[(layer * 64 + c) * 512 + slot], S);
        atomicAdd(&g_psumsq[(layer * 64 + c) * 512 + slot], Q);
    }
}

// ---------------- layer1 fused: conv(1->16) + BN + ReLU + pool2 --------------
// Block 128 threads. Pooled tile 16x16 (= conv tile 32x32). 224x224 exact fit.
__launch_bounds__(128)
__global__ void conv1_pool_k(const float* __restrict__ in, const float* __restrict__ w,
                             const float* __restrict__ bias, float* __restrict__ out) {
    const int H = 224, W = 224;
    __shared__ float s_in[34][35];
    __shared__ float s_w[16 * 9];
    __shared__ float s_a[16], s_t[16];
    const int n = blockIdx.z;
    const int tx = blockIdx.x % 7, ty = blockIdx.x / 7;
    const int tid = threadIdx.x;

    // FIX (R2 bug): strided load — 144 > blockDim(128); tail was uninitialized
    for (int i = tid; i < 144; i += 128) s_w[i] = w[i];
    if (tid < 16) {
        float a = g_scale[tid];
        s_a[tid] = a;
        s_t[tid] = bias[tid] * a + g_shift[tid];
    }
    const int gx0 = tx * 32 - 1, gy0 = ty * 32 - 1;
    const float* ip = in + (size_t)n * H * W;
    for (int i = tid; i < 34 * 34; i += 128) {
        int r = i / 34, c = i % 34;
        int gy = gy0 + r, gx = gx0 + c;
        float v = 0.f;
        if (gy >= 0 && gy < H && gx >= 0 && gx < W) v = ip[(size_t)gy * W + gx];
        s_in[r][c] = v;
    }
    __syncthreads();

    const int pxp = (tid & 7) * 2;   // pooled x within tile: 0,2,..,14
    const int pyp = tid >> 3;        // pooled y within tile: 0..15
    const int cx = pxp * 2;          // conv x local (0..28)
    const int cy = pyp * 2;          // conv y local (0..30)

    float iv[4][6];
    #pragma unroll
    for (int r = 0; r < 4; r++)
        #pragma unroll
        for (int c = 0; c < 6; c++)
            iv[r][c] = s_in[cy + r][cx + c];

    const int gxp = tx * 16 + pxp;
    const int gyp = ty * 16 + pyp;

    #pragma unroll
    for (int co = 0; co < 16; co++) {
        float w0 = s_w[co * 9 + 0], w1 = s_w[co * 9 + 1], w2 = s_w[co * 9 + 2];
        float w3 = s_w[co * 9 + 3], w4 = s_w[co * 9 + 4], w5 = s_w[co * 9 + 5];
        float w6 = s_w[co * 9 + 6], w7 = s_w[co * 9 + 7], w8 = s_w[co * 9 + 8];
        float a = s_a[co], t = s_t[co];
        float v[2][4];
        #pragma unroll
        for (int r = 0; r < 2; r++)
            #pragma unroll
            for (int c = 0; c < 4; c++) {
                float s = iv[r + 0][c + 0] * w0 + iv[r + 0][c + 1] * w1 + iv[r + 0][c + 2] * w2
                        + iv[r + 1][c + 0] * w3 + iv[r + 1][c + 1] * w4 + iv[r + 1][c + 2] * w5
                        + iv[r + 2][c + 0] * w6 + iv[r + 2][c + 1] * w7 + iv[r + 2][c + 2] * w8;
                v[r][c] = fmaf(s, a, t);
            }
        float p0 = fmaxf(fmaxf(v[0][0], v[0][1]), fmaxf(v[1][0], v[1][1]));
        float p1 = fmaxf(fmaxf(v[0][2], v[0][3]), fmaxf(v[1][2], v[1][3]));
        size_t base = (((size_t)n * 16 + co) * 112 + gyp) * (size_t)112 + gxp;
        out[base + 0] = fmaxf(p0, 0.f);
        out[base + 1] = fmaxf(p1, 0.f);
    }
}

// ---------------- BN affine + ReLU + 2x2 maxpool (layers 2,3) ----------------
__global__ void bn_relu_pool_k(const float* __restrict__ in, float* __restrict__ out,
                               int C, int H, int W, long long total) {
    long long idx = (long long)blockIdx.x * blockDim.x + threadIdx.x;
    if (idx >= total) return;
    int W2 = W >> 1, H2 = H >> 1;
    int x2 = (int)(idx % W2);
    long long r = idx / W2;
    int y2 = (int)(r % H2); r /= H2;
    int c  = (int)(r % C);
    int n  = (int)(r / C);
    const float2* p0 = (const float2*)(in + (((size_t)n * C + c) * H + 2 * y2) * (size_t)W) + x2;
    const float2* p1 = (const float2*)((const float*)p0 + W);
    float2 u = *p0, d = *p1;
    float a = g_scale[c], s = g_shift[c];
    float v0 = fmaf(u.x, a, s);
    float v1 = fmaf(u.y, a, s);
    float v2 = fmaf(d.x, a, s);
    float v3 = fmaf(d.y, a, s);
    float m = fmaxf(fmaxf(v0, v1), fmaxf(v2, v3));
    out[idx] = fmaxf(m, 0.f);
}

// ---------------- head: GAP + fc1 + LN + quantum circuit + fc2/fc3 -----------
__global__ void head_k(const float* __restrict__ pooled,   // (B,64,28,28)
                       const float* __restrict__ fc1_w, const float* __restrict__ fc1_b,
                       const float* __restrict__ ln_g,  const float* __restrict__ ln_b,
                       const float* __restrict__ qp,
                       const float* __restrict__ fc2_w, const float* __restrict__ fc2_b,
                       const float* __restrict__ fc3_w, const float* __restrict__ fc3_b,
                       float* __restrict__ out) {
    const int n = blockIdx.x;
    const int tid = threadIdx.x;
    const int warp = tid >> 5, lane = tid & 31;
    __shared__ float chm[64];
    __shared__ float qin[5];
    __shared__ float qres;

    const float* base = pooled + (size_t)n * 64 * 784;
    for (int j = 0; j < 8; j++) {
        int c = warp * 8 + j;
        const float* p = base + (size_t)c * 784;
        float s = 0.f;
        for (int i = lane; i < 784; i += 32) s += p[i];
        #pragma unroll
        for (int o = 16; o > 0; o >>= 1) s += __shfl_down_sync(0xffffffffu, s, o);
        if (lane == 0) chm[c] = s * (1.0f / 784.0f);
    }
    __syncthreads();

    if (tid == 0) {
        float h[5];
        #pragma unroll
        for (int o = 0; o < 5; o++) {
            float s = fc1_b[o];
            for (int i = 0; i < 64; i++) s += chm[i] * fc1_w[i * 5 + o];
            h[o] = s;
        }
        float mu = 0.f;
        #pragma unroll
        for (int o = 0; o < 5; o++) mu += h[o];
        mu *= 0.2f;
        float var = 0.f;
        #pragma unroll
        for (int o = 0; o < 5; o++) { float d = h[o] - mu; var += d * d; }
        var *= 0.2f;
        float r = rsqrtf(var + 1e-5f);
        #pragma unroll
        for (int o = 0; o < 5; o++) qin[o] = ln_g[o] * (h[o] - mu) * r + ln_b[o];
    }
    __syncthreads();

    // 5-qubit statevector: amplitude per lane (warp 0). wire i -> bit (1<<(4-i))
    if (warp == 0) {
        float are = (lane == 0) ? 1.f : 0.f, aim = 0.f;
        const unsigned fm = 0xffffffffu;
        for (int l = 0; l < 3; l++) {
            #pragma unroll
            for (int i = 0; i < 5; i++) {
                int m = 1 << (4 - i);
                float sn, cs; sincosf(qin[i] * 0.5f, &sn, &cs);
                float pre = __shfl_xor_sync(fm, are, m);
                float pim = __shfl_xor_sync(fm, aim, m);
                float nre = cs * are + sn * pim;
                float nim = cs * aim - sn * pre;
                are = nre; aim = nim;
            }
            #pragma unroll
            for (int i = 0; i < 5; i++) {
                int m = 1 << (4 - i);
                float sy, cy; sincosf(qp[l * 10 + i] * 0.5f, &sy, &cy);
                float pre = __shfl_xor_sync(fm, are, m);
                float pim = __shfl_xor_sync(fm, aim, m);
                float sgn = (lane & m) ? sy : -sy;
                float nre = cy * are + sgn * pre;
                float nim = cy * aim + sgn * pim;
                float sz, cz; sincosf(qp[l * 10 + i + 5] * 0.5f, &sz, &cz);
                float zg = (lane & m) ? -sz : sz;
                are = nre * cz + zg * nim;
                aim = nim * cz - zg * nre;
            }
            const int cw[5] = {0, 1, 2, 3, 4};
            const int tw[5] = {1, 2, 3, 4, 0};
            #pragma unroll
            for (int k = 0; k < 5; k++) {
                int mc = 1 << (4 - cw[k]);
                int mt = 1 << (4 - tw[k]);
                int src = (lane & mc) ? (lane ^ mt) : lane;
                are = __shfl_sync(fm, are, src);
                aim = __shfl_sync(fm, aim, src);
            }
        }
        float p = are * are + aim * aim;
        float sgn = (__popc(lane & 28) & 1) ? -1.f : 1.f;
        float v = p * sgn;
        #pragma unroll
        for (int o = 16; o > 0; o >>= 1) v += __shfl_down_sync(fm, v, o);
        if (lane == 0) qres = v;
    }
    __syncthreads();

    if (tid == 0) {
        float q = qres;
        float l0 = fc3_b[0], l1 = fc3_b[1];
        for (int j = 0; j < 32; j++) {
            float h2 = fmaxf(q * fc2_w[j] + fc2_b[j], 0.f);
            l0 += h2 * fc3_w[j * 2 + 0];
            l1 += h2 * fc3_w[j * 2 + 1];
        }
        float mx = fmaxf(l0, l1);
        float lse = mx + logf(expf(l0 - mx) + expf(l1 - mx));
        out[n * 2 + 0] = l0 - lse;
        out[n * 2 + 1] = l1 - lse;
    }
}

// ---------------- host launcher ----------------------------------------------
extern "C" void kernel_launch(void* const* d_in, const int* in_sizes, int n_in,
                              void* d_out, int out_size) {
    const float* x    = (const float*)d_in[0];
    const float* c1w  = (const float*)d_in[1];
    const float* c1b  = (const float*)d_in[2];
    const float* bn1g = (const float*)d_in[3];
    const float* bn1b = (const float*)d_in[4];
    const float* c2w  = (const float*)d_in[5];
    const float* c2b  = (const float*)d_in[6];
    const float* bn2g = (const float*)d_in[7];
    const float* bn2b = (const float*)d_in[8];
    const float* c3w  = (const float*)d_in[9];
    const float* c3b  = (const float*)d_in[10];
    const float* bn3g = (const float*)d_in[11];
    const float* bn3b = (const float*)d_in[12];
    const float* fc1w = (const float*)d_in[13];
    const float* fc1b = (const float*)d_in[14];
    const float* lng  = (const float*)d_in[15];
    const float* lnb  = (const float*)d_in[16];
    const float* qp   = (const float*)d_in[17];
    const float* fc2w = (const float*)d_in[18];
    const float* fc2b = (const float*)d_in[19];
    const float* fc3w = (const float*)d_in[20];
    const float* fc3b = (const float*)d_in[21];
    float* out = (float*)d_out;

    float *conv, *poolA, *poolB;
    cudaGetSymbolAddress((void**)&conv,  g_conv);
    cudaGetSymbolAddress((void**)&poolA, g_poolA);
    cudaGetSymbolAddress((void**)&poolB, g_poolB);

    const int B = 256;

    zero_partials_k<<<(3 * 64 * 512 + 511) / 512, 512>>>();

    // ---- Layer 1: conv(1->16) @224, stats pass (no store) + fused pool pass ----
    {
        int H = 224, W = 224, CO = 16;
        int txs = (W + 31) / 32, tys = (H + 15) / 16;
        conv3x3_k<1, false><<<dim3(txs * tys, CO / 8, B), 128>>>(x, c1w, c1b, nullptr, CO, H, W, txs, 0);
        finalize_k<<<1, 64>>>(bn1g, bn1b, CO, 0, 1.0 / ((double)B * H * W));
        conv1_pool_k<<<dim3(49, 1, B), 128>>>(x, c1w, c1b, poolA);
    }
    // ---- Layer 2: conv(16->32) @112 with fused stats ----
    {
        int H = 112, W = 112, CO = 32;
        int txs = (W + 31) / 32, tys = (H + 15) / 16;
        conv3x3_k<16, true><<<dim3(txs * tys, CO / 8, B), 128>>>(poolA, c2w, c2b, conv, CO, H, W, txs, 1);
        finalize_k<<<1, 64>>>(bn2g, bn2b, CO, 1, 1.0 / ((double)B * H * W));
        long long tot = (long long)B * CO * (H / 2) * (W / 2);
        bn_relu_pool_k<<<(unsigned)((tot + 255) / 256), 256>>>(conv, poolB, CO, H, W, tot);
    }
    // ---- Layer 3: conv(32->64) @56 with fused stats ----
    {
        int H = 56, W = 56, CO = 64;
        int txs = (W + 31) / 32, tys = (H + 15) / 16;
        conv3x3_k<32, true><<<dim3(txs * tys, CO / 8, B), 128>>>(poolB, c3w, c3b, conv, CO, H, W, txs, 2);
        finalize_k<<<1, 64>>>(bn3g, bn3b, CO, 2, 1.0 / ((double)B * H * W));
        long long tot = (long long)B * CO * (H / 2) * (W / 2);
        bn_relu_pool_k<<<(unsigned)((tot + 255) / 256), 256>>>(conv, poolA, CO, H, W, tot);
    }
    // ---- Head ----
    head_k<<<B, 256>>>(poolA, fc1w, fc1b, lng, lnb, qp, fc2w, fc2b, fc3w, fc3b, out);
}

// round 4
// speedup vs baseline: 1.2591x; 1.0419x over previous
#include <cuda_runtime.h>
#include <math.h>
#include <stdint.h>

// ---------------- scratch (static device memory; no allocs allowed) ----------
__device__ float g_conv[102760448];   // max stored conv out: 256*32*112*112 (411 MB)
__device__ float g_poolA[51380224];   // 256*16*112*112 (205 MB); also pool3 out (51 MB)
__device__ float g_poolB[25690112];   // 256*32*56*56  (103 MB)
__device__ float g_psum[3 * 64 * 512];
__device__ float g_psumsq[3 * 64 * 512];
__device__ float g_scale[64];
__device__ float g_shift[64];

// ---------------- zero partial-stat buffers ----------------------------------
__global__ void zero_partials_k() {
    int i = blockIdx.x * blockDim.x + threadIdx.x;
    if (i < 3 * 64 * 512) { g_psum[i] = 0.f; g_psumsq[i] = 0.f; }
}

// ---------------- finalize: reduce partials -> scale/shift --------------------
__global__ void finalize_k(const float* __restrict__ gam, const float* __restrict__ bet,
                           int C, int layer, double inv_cnt) {
    int c = threadIdx.x;
    if (c < C) {
        const float* ps = &g_psum[(layer * 64 + c) * 512];
        const float* pq = &g_psumsq[(layer * 64 + c) * 512];
        double S = 0.0, Q = 0.0;
        for (int i = 0; i < 512; i++) { S += (double)ps[i]; Q += (double)pq[i]; }
        double mean = S * inv_cnt;
        double var = Q * inv_cnt - mean * mean;
        float sc = gam[c] * rsqrtf((float)var + 1e-5f);
        g_scale[c] = sc;
        g_shift[c] = bet[c] - sc * (float)mean;
    }
}

// ---------------- direct 3x3 conv, SAME pad, stride 1, fused BN stats --------
// Block = 128 threads. Tile = 32(x) x 16(y) outputs; each thread: 4 px x 16 co.
// Double-buffered input tile: one __syncthreads per ci; LDG(ci+1) overlaps FMA(ci).
template<int CI, bool STORE>
__launch_bounds__(128)
__global__ void conv3x3_k(const float* __restrict__ in, const float* __restrict__ w,
                          const float* __restrict__ bias, float* __restrict__ out,
                          int CO, int H, int W, int tiles_x, int layer) {
    __shared__ float s_in[2][18][35];
    __shared__ float s_w[CI * 16 * 9];
    __shared__ float redS[16][4], redQ[16][4];
    const int n   = blockIdx.z;
    const int cog = blockIdx.y;            // group of 16 output channels
    const int tile = blockIdx.x;
    const int tx = tile % tiles_x, ty = tile / tiles_x;
    const int tid = threadIdx.x;
    const int warp = tid >> 5, lane = tid & 31;

    for (int i = tid; i < CI * 16 * 9; i += 128)
        s_w[i] = w[(size_t)(cog * 16) * CI * 9 + i];

    const int px = (tid & 7) * 4;
    const int py = tid >> 3;
    const int gx0 = tx * 32 - 1;
    const int gy0 = ty * 16 - 1;

    // tile loader: 18x34 halo tile for channel ci into buffer b
    const int lr0 = tid / 34, lc = tid % 34;       // rows 0..3 base (128/34)
    const bool interior = (gx0 >= 0) && (gy0 >= 0) && (gx0 + 33 < W) && (gy0 + 17 < H);

    auto load_tile = [&](int ci, int b) {
        const float* ip = in + ((size_t)n * CI + ci) * (size_t)H * W;
        if (interior) {
            #pragma unroll
            for (int rr = 0; rr < 5; rr++) {
                int r = lr0 + rr * 3;              // covers rows 0..14 for lr0 in 0..2... need full 18
                (void)r;
            }
            // 612 elements, 128 threads: strided flat loop (no bounds checks)
            for (int i = tid; i < 18 * 34; i += 128) {
                int r = i / 34, c = i % 34;
                s_in[b][r][c] = ip[(size_t)(gy0 + r) * W + (gx0 + c)];
            }
        } else {
            for (int i = tid; i < 18 * 34; i += 128) {
                int r = i / 34, c = i % 34;
                int gy = gy0 + r, gx = gx0 + c;
                float v = 0.f;
                if (gy >= 0 && gy < H && gx >= 0 && gx < W) v = ip[(size_t)gy * W + gx];
                s_in[b][r][c] = v;
            }
        }
    };

    float acc[16][4];
    #pragma unroll
    for (int co = 0; co < 16; co++)
        #pragma unroll
        for (int p = 0; p < 4; p++) acc[co][p] = 0.f;

    load_tile(0, 0);
    __syncthreads();

    for (int ci = 0; ci < CI; ci++) {
        const int cur = ci & 1;
        if (ci + 1 < CI) load_tile(ci + 1, cur ^ 1);

        float iv[3][6];
        #pragma unroll
        for (int ky = 0; ky < 3; ky++)
            #pragma unroll
            for (int j = 0; j < 6; j++)
                iv[ky][j] = s_in[cur][py + ky][px + j];

        #pragma unroll
        for (int co = 0; co < 16; co++) {
            const float* wp = &s_w[(co * CI + ci) * 9];
            #pragma unroll
            for (int ky = 0; ky < 3; ky++)
                #pragma unroll
                for (int kx = 0; kx < 3; kx++) {
                    float wv = wp[ky * 3 + kx];
                    #pragma unroll
                    for (int p = 0; p < 4; p++)
                        acc[co][p] = fmaf(iv[ky][kx + p], wv, acc[co][p]);
                }
        }
        __syncthreads();
    }

    // epilogue: optional store + per-channel stats accumulation
    const int y = ty * 16 + py;
    const bool yv = (y < H);
    #pragma unroll
    for (int co = 0; co < 16; co++) {
        int cg = cog * 16 + co;
        float b = bias[cg];
        size_t base = (((size_t)n * CO + cg) * H + y) * (size_t)W;
        float s = 0.f, q = 0.f;
        #pragma unroll
        for (int p = 0; p < 4; p++) {
            int x = tx * 32 + px + p;
            float v = acc[co][p] + b;
            bool valid = yv && (x < W);
            if (STORE && valid) out[base + x] = v;
            if (valid) { s += v; q += v * v; }
        }
        #pragma unroll
        for (int o = 16; o > 0; o >>= 1) {
            s += __shfl_down_sync(0xffffffffu, s, o);
            q += __shfl_down_sync(0xffffffffu, q, o);
        }
        if (lane == 0) { redS[co][warp] = s; redQ[co][warp] = q; }
    }
    __syncthreads();
    if (tid < 16) {
        float S = redS[tid][0] + redS[tid][1] + redS[tid][2] + redS[tid][3];
        float Q = redQ[tid][0] + redQ[tid][1] + redQ[tid][2] + redQ[tid][3];
        int slot = (blockIdx.x + blockIdx.z * 977) & 511;
        int c = cog * 16 + tid;
        atomicAdd(&g_psum[(layer * 64 + c) * 512 + slot], S);
        atomicAdd(&g_psumsq[(layer * 64 + c) * 512 + slot], Q);
    }
}

// ---------------- layer1 fused: conv(1->16) + BN + ReLU + pool2 --------------
__launch_bounds__(128)
__global__ void conv1_pool_k(const float* __restrict__ in, const float* __restrict__ w,
                             const float* __restrict__ bias, float* __restrict__ out) {
    const int H = 224, W = 224;
    __shared__ float s_in[34][35];
    __shared__ float s_w[16 * 9];
    __shared__ float s_a[16], s_t[16];
    const int n = blockIdx.z;
    const int tx = blockIdx.x % 7, ty = blockIdx.x / 7;
    const int tid = threadIdx.x;

    for (int i = tid; i < 144; i += 128) s_w[i] = w[i];
    if (tid < 16) {
        float a = g_scale[tid];
        s_a[tid] = a;
        s_t[tid] = bias[tid] * a + g_shift[tid];
    }
    const int gx0 = tx * 32 - 1, gy0 = ty * 32 - 1;
    const float* ip = in + (size_t)n * H * W;
    for (int i = tid; i < 34 * 34; i += 128) {
        int r = i / 34, c = i % 34;
        int gy = gy0 + r, gx = gx0 + c;
        float v = 0.f;
        if (gy >= 0 && gy < H && gx >= 0 && gx < W) v = ip[(size_t)gy * W + gx];
        s_in[r][c] = v;
    }
    __syncthreads();

    const int pxp = (tid & 7) * 2;
    const int pyp = tid >> 3;
    const int cx = pxp * 2;
    const int cy = pyp * 2;

    float iv[4][6];
    #pragma unroll
    for (int r = 0; r < 4; r++)
        #pragma unroll
        for (int c = 0; c < 6; c++)
            iv[r][c] = s_in[cy + r][cx + c];

    const int gxp = tx * 16 + pxp;
    const int gyp = ty * 16 + pyp;

    #pragma unroll
    for (int co = 0; co < 16; co++) {
        float w0 = s_w[co * 9 + 0], w1 = s_w[co * 9 + 1], w2 = s_w[co * 9 + 2];
        float w3 = s_w[co * 9 + 3], w4 = s_w[co * 9 + 4], w5 = s_w[co * 9 + 5];
        float w6 = s_w[co * 9 + 6], w7 = s_w[co * 9 + 7], w8 = s_w[co * 9 + 8];
        float a = s_a[co], t = s_t[co];
        float v[2][4];
        #pragma unroll
        for (int r = 0; r < 2; r++)
            #pragma unroll
            for (int c = 0; c < 4; c++) {
                float s = iv[r + 0][c + 0] * w0 + iv[r + 0][c + 1] * w1 + iv[r + 0][c + 2] * w2
                        + iv[r + 1][c + 0] * w3 + iv[r + 1][c + 1] * w4 + iv[r + 1][c + 2] * w5
                        + iv[r + 2][c + 0] * w6 + iv[r + 2][c + 1] * w7 + iv[r + 2][c + 2] * w8;
                v[r][c] = fmaf(s, a, t);
            }
        float p0 = fmaxf(fmaxf(v[0][0], v[0][1]), fmaxf(v[1][0], v[1][1]));
        float p1 = fmaxf(fmaxf(v[0][2], v[0][3]), fmaxf(v[1][2], v[1][3]));
        size_t base = (((size_t)n * 16 + co) * 112 + gyp) * (size_t)112 + gxp;
        out[base + 0] = fmaxf(p0, 0.f);
        out[base + 1] = fmaxf(p1, 0.f);
    }
}

// ---------------- BN affine + ReLU + 2x2 maxpool (layers 2,3) ----------------
__global__ void bn_relu_pool_k(const float* __restrict__ in, float* __restrict__ out,
                               int C, int H, int W, long long total) {
    long long idx = (long long)blockIdx.x * blockDim.x + threadIdx.x;
    if (idx >= total) return;
    int W2 = W >> 1, H2 = H >> 1;
    int x2 = (int)(idx % W2);
    long long r = idx / W2;
    int y2 = (int)(r % H2); r /= H2;
    int c  = (int)(r % C);
    int n  = (int)(r / C);
    const float2* p0 = (const float2*)(in + (((size_t)n * C + c) * H + 2 * y2) * (size_t)W) + x2;
    const float2* p1 = (const float2*)((const float*)p0 + W);
    float2 u = *p0, d = *p1;
    float a = g_scale[c], s = g_shift[c];
    float v0 = fmaf(u.x, a, s);
    float v1 = fmaf(u.y, a, s);
    float v2 = fmaf(d.x, a, s);
    float v3 = fmaf(d.y, a, s);
    float m = fmaxf(fmaxf(v0, v1), fmaxf(v2, v3));
    out[idx] = fmaxf(m, 0.f);
}

// ---------------- head: GAP + fc1 + LN + quantum circuit + fc2/fc3 -----------
__global__ void head_k(const float* __restrict__ pooled,   // (B,64,28,28)
                       const float* __restrict__ fc1_w, const float* __restrict__ fc1_b,
                       const float* __restrict__ ln_g,  const float* __restrict__ ln_b,
                       const float* __restrict__ qp,
                       const float* __restrict__ fc2_w, const float* __restrict__ fc2_b,
                       const float* __restrict__ fc3_w, const float* __restrict__ fc3_b,
                       float* __restrict__ out) {
    const int n = blockIdx.x;
    const int tid = threadIdx.x;
    const int warp = tid >> 5, lane = tid & 31;
    __shared__ float chm[64];
    __shared__ float qin[5];
    __shared__ float qres;

    const float* base = pooled + (size_t)n * 64 * 784;
    for (int j = 0; j < 8; j++) {
        int c = warp * 8 + j;
        const float* p = base + (size_t)c * 784;
        float s = 0.f;
        for (int i = lane; i < 784; i += 32) s += p[i];
        #pragma unroll
        for (int o = 16; o > 0; o >>= 1) s += __shfl_down_sync(0xffffffffu, s, o);
        if (lane == 0) chm[c] = s * (1.0f / 784.0f);
    }
    __syncthreads();

    if (tid == 0) {
        float h[5];
        #pragma unroll
        for (int o = 0; o < 5; o++) {
            float s = fc1_b[o];
            for (int i = 0; i < 64; i++) s += chm[i] * fc1_w[i * 5 + o];
            h[o] = s;
        }
        float mu = 0.f;
        #pragma unroll
        for (int o = 0; o < 5; o++) mu += h[o];
        mu *= 0.2f;
        float var = 0.f;
        #pragma unroll
        for (int o = 0; o < 5; o++) { float d = h[o] - mu; var += d * d; }
        var *= 0.2f;
        float r = rsqrtf(var + 1e-5f);
        #pragma unroll
        for (int o = 0; o < 5; o++) qin[o] = ln_g[o] * (h[o] - mu) * r + ln_b[o];
    }
    __syncthreads();

    // 5-qubit statevector: amplitude per lane (warp 0). wire i -> bit (1<<(4-i))
    if (warp == 0) {
        float are = (lane == 0) ? 1.f : 0.f, aim = 0.f;
        const unsigned fm = 0xffffffffu;
        for (int l = 0; l < 3; l++) {
            #pragma unroll
            for (int i = 0; i < 5; i++) {
                int m = 1 << (4 - i);
                float sn, cs; sincosf(qin[i] * 0.5f, &sn, &cs);
                float pre = __shfl_xor_sync(fm, are, m);
                float pim = __shfl_xor_sync(fm, aim, m);
                float nre = cs * are + sn * pim;
                float nim = cs * aim - sn * pre;
                are = nre; aim = nim;
            }
            #pragma unroll
            for (int i = 0; i < 5; i++) {
                int m = 1 << (4 - i);
                float sy, cy; sincosf(qp[l * 10 + i] * 0.5f, &sy, &cy);
                float pre = __shfl_xor_sync(fm, are, m);
                float pim = __shfl_xor_sync(fm, aim, m);
                float sgn = (lane & m) ? sy : -sy;
                float nre = cy * are + sgn * pre;
                float nim = cy * aim + sgn * pim;
                float sz, cz; sincosf(qp[l * 10 + i + 5] * 0.5f, &sz, &cz);
                float zg = (lane & m) ? -sz : sz;
                are = nre * cz + zg * nim;
                aim = nim * cz - zg * nre;
            }
            const int cw[5] = {0, 1, 2, 3, 4};
            const int tw[5] = {1, 2, 3, 4, 0};
            #pragma unroll
            for (int k = 0; k < 5; k++) {
                int mc = 1 << (4 - cw[k]);
                int mt = 1 << (4 - tw[k]);
                int src = (lane & mc) ? (lane ^ mt) : lane;
                are = __shfl_sync(fm, are, src);
                aim = __shfl_sync(fm, aim, src);
            }
        }
        float p = are * are + aim * aim;
        float sgn = (__popc(lane & 28) & 1) ? -1.f : 1.f;
        float v = p * sgn;
        #pragma unroll
        for (int o = 16; o > 0; o >>= 1) v += __shfl_down_sync(fm, v, o);
        if (lane == 0) qres = v;
    }
    __syncthreads();

    if (tid == 0) {
        float q = qres;
        float l0 = fc3_b[0], l1 = fc3_b[1];
        for (int j = 0; j < 32; j++) {
            float h2 = fmaxf(q * fc2_w[j] + fc2_b[j], 0.f);
            l0 += h2 * fc3_w[j * 2 + 0];
            l1 += h2 * fc3_w[j * 2 + 1];
        }
        float mx = fmaxf(l0, l1);
        float lse = mx + logf(expf(l0 - mx) + expf(l1 - mx));
        out[n * 2 + 0] = l0 - lse;
        out[n * 2 + 1] = l1 - lse;
    }
}

// ---------------- host launcher ----------------------------------------------
extern "C" void kernel_launch(void* const* d_in, const int* in_sizes, int n_in,
                              void* d_out, int out_size) {
    const float* x    = (const float*)d_in[0];
    const float* c1w  = (const float*)d_in[1];
    const float* c1b  = (const float*)d_in[2];
    const float* bn1g = (const float*)d_in[3];
    const float* bn1b = (const float*)d_in[4];
    const float* c2w  = (const float*)d_in[5];
    const float* c2b  = (const float*)d_in[6];
    const float* bn2g = (const float*)d_in[7];
    const float* bn2b = (const float*)d_in[8];
    const float* c3w  = (const float*)d_in[9];
    const float* c3b  = (const float*)d_in[10];
    const float* bn3g = (const float*)d_in[11];
    const float* bn3b = (const float*)d_in[12];
    const float* fc1w = (const float*)d_in[13];
    const float* fc1b = (const float*)d_in[14];
    const float* lng  = (const float*)d_in[15];
    const float* lnb  = (const float*)d_in[16];
    const float* qp   = (const float*)d_in[17];
    const float* fc2w = (const float*)d_in[18];
    const float* fc2b = (const float*)d_in[19];
    const float* fc3w = (const float*)d_in[20];
    const float* fc3b = (const float*)d_in[21];
    float* out = (float*)d_out;

    float *conv, *poolA, *poolB;
    cudaGetSymbolAddress((void**)&conv,  g_conv);
    cudaGetSymbolAddress((void**)&poolA, g_poolA);
    cudaGetSymbolAddress((void**)&poolB, g_poolB);

    const int B = 256;

    zero_partials_k<<<(3 * 64 * 512 + 511) / 512, 512>>>();

    // ---- Layer 1: conv(1->16) @224, stats pass (no store) + fused pool pass ----
    {
        int H = 224, W = 224, CO = 16;
        int txs = (W + 31) / 32, tys = (H + 15) / 16;
        conv3x3_k<1, false><<<dim3(txs * tys, 1, B), 128>>>(x, c1w, c1b, nullptr, CO, H, W, txs, 0);
        finalize_k<<<1, 64>>>(bn1g, bn1b, CO, 0, 1.0 / ((double)B * H * W));
        conv1_pool_k<<<dim3(49, 1, B), 128>>>(x, c1w, c1b, poolA);
    }
    // ---- Layer 2: conv(16->32) @112 with fused stats ----
    {
        int H = 112, W = 112, CO = 32;
        int txs = (W + 31) / 32, tys = (H + 15) / 16;
        conv3x3_k<16, true><<<dim3(txs * tys, CO / 16, B), 128>>>(poolA, c2w, c2b, conv, CO, H, W, txs, 1);
        finalize_k<<<1, 64>>>(bn2g, bn2b, CO, 1, 1.0 / ((double)B * H * W));
        long long tot = (long long)B * CO * (H / 2) * (W / 2);
        bn_relu_pool_k<<<(unsigned)((tot + 255) / 256), 256>>>(conv, poolB, CO, H, W, tot);
    }
    // ---- Layer 3: conv(32->64) @56 with fused stats ----
    {
        int H = 56, W = 56, CO = 64;
        int txs = (W + 31) / 32, tys = (H + 15) / 16;
        conv3x3_k<32, true><<<dim3(txs * tys, CO / 16, B), 128>>>(poolB, c3w, c3b, conv, CO, H, W, txs, 2);
        finalize_k<<<1, 64>>>(bn3g, bn3b, CO, 2, 1.0 / ((double)B * H * W));
        long long tot = (long long)B * CO * (H / 2) * (W / 2);
        bn_relu_pool_k<<<(unsigned)((tot + 255) / 256), 256>>>(conv, poolA, CO, H, W, tot);
    }
    // ---- Head ----
    head_k<<<B, 256>>>(poolA, fc1w, fc1b, lng, lnb, qp, fc2w, fc2b, fc3w, fc3b, out);
}